// round 10
// baseline (speedup 1.0000x reference)
#include <cuda_runtime.h>
#include <cuda_fp16.h>
#include <math.h>
#include <stdint.h>

#define BB 64
#define TT 512
#define VV 256
#define MEM 1024
#define G4 4096

// ---------------- device scratch ----------------
__device__ float g_Zx[(size_t)TT * BB * G4];            // input-side z (+bias), gate-permuted cols, fp32
__device__ float g_hall[(size_t)TT * BB * MEM];         // per-layer h sequence fp32 (reused)
__device__ float g_c[2][BB * MEM];                      // cell state per layer, fp32
__device__ uint32_t g_h2[2][2][BB * 512];               // h state as packed half2 (pairs along k), double-buffered
__device__ float g_hfin[2][BB * MEM];                   // final-step h, fp32
__device__ uint32_t g_W0h[((VV + MEM) / 2) * G4];       // W0 packed half2 pairs along k, gate-permuted cols
__device__ uint32_t g_W1h[((2 * MEM) / 2) * G4];        // W1 same
__device__ __half g_W0t[(size_t)G4 * (VV + MEM)];       // W0^T [n][k] halves, gate-permuted n
__device__ __half g_W1t[(size_t)G4 * (2 * MEM)];        // W1^T
__device__ __half g_Wot[(size_t)VV * MEM];              // W_out^T [n][k] halves
__device__ float g_b0p[G4];
__device__ float g_b1p[G4];
__device__ volatile int g_arrive[128];

__device__ __forceinline__ float sigm(float x) { return 1.0f / (1.0f + expf(-x)); }
__device__ __forceinline__ uint32_t pk(float a, float b) {
    __half2 h = __floats2half2_rn(a, b);
    return *(uint32_t*)&h;
}
__device__ __forceinline__ uint32_t smem_u32(const void* p) {
    uint32_t a;
    asm("{ .reg .u64 t; cvta.to.shared.u64 t, %1; cvt.u32.u64 %0, t; }" : "=r"(a) : "l"(p));
    return a;
}
__device__ __forceinline__ void cpa16(uint32_t dst, const void* src) {
    asm volatile("cp.async.cg.shared.global [%0], [%1], 16;" :: "r"(dst), "l"(src));
}
__device__ __forceinline__ void cpa_commit() { asm volatile("cp.async.commit_group;" ::: "memory"); }
#define WAITG(n) asm volatile("cp.async.wait_group %0;" :: "n"(n) : "memory")

// m16n8k16 fp16 mma, fp32 accum
__device__ __forceinline__ void mma16(float* d, uint32_t a0, uint32_t a1, uint32_t a2, uint32_t a3,
                                      uint32_t b0, uint32_t b1) {
    asm volatile("mma.sync.aligned.m16n8k16.row.col.f32.f16.f16.f32 "
                 "{%0,%1,%2,%3}, {%4,%5,%6,%7}, {%8,%9}, {%0,%1,%2,%3};"
                 : "+f"(d[0]), "+f"(d[1]), "+f"(d[2]), "+f"(d[3])
                 : "r"(a0), "r"(a1), "r"(a2), "r"(a3), "r"(b0), "r"(b1));
}

// ---------------- init ----------------
__global__ void init_state(const float* __restrict__ s0, const float* __restrict__ s1) {
    int i = blockIdx.x * 256 + threadIdx.x;
    int b = i >> 10, u = i & 1023;
    g_c[0][i] = s0[b * 2 * MEM + u];
    g_c[1][i] = s1[b * 2 * MEM + u];
    if (u < 512) {
        int kp = u;
        g_h2[0][0][b * 512 + kp] = pk(s0[b * 2 * MEM + MEM + 2 * kp], s0[b * 2 * MEM + MEM + 2 * kp + 1]);
        g_h2[1][0][b * 512 + kp] = pk(s1[b * 2 * MEM + MEM + 2 * kp], s1[b * 2 * MEM + MEM + 2 * kp + 1]);
    }
    if (blockIdx.x == 0 && threadIdx.x < 128) g_arrive[threadIdx.x] = 0;
}

// ---------------- gate-permuted packed-half2 K-major weights + fp32 permuted biases ----------------
__global__ void permute_w(const float* __restrict__ W0, const float* __restrict__ b0,
                          const float* __restrict__ W1, const float* __restrict__ b1) {
    size_t i = (size_t)blockIdx.x * 256 + threadIdx.x;
    const size_t n0 = (size_t)((VV + MEM) / 2) * MEM;
    const size_t n1 = (size_t)((2 * MEM) / 2) * MEM;
    if (i < n0) {
        size_t kp = i >> 10; int u = (int)(i & 1023);
        const float* s = W0 + (size_t)(2 * kp) * G4 + u;
        uint4 v;
        v.x = pk(s[0],    s[G4]);
        v.y = pk(s[1024], s[G4 + 1024]);
        v.z = pk(s[2048], s[G4 + 2048]);
        v.w = pk(s[3072], s[G4 + 3072]);
        *(uint4*)&g_W0h[kp * G4 + (size_t)u * 4] = v;
    } else if (i < n0 + n1) {
        size_t k = i - n0;
        size_t kp = k >> 10; int u = (int)(k & 1023);
        const float* s = W1 + (size_t)(2 * kp) * G4 + u;
        uint4 v;
        v.x = pk(s[0],    s[G4]);
        v.y = pk(s[1024], s[G4 + 1024]);
        v.z = pk(s[2048], s[G4 + 2048]);
        v.w = pk(s[3072], s[G4 + 3072]);
        *(uint4*)&g_W1h[kp * G4 + (size_t)u * 4] = v;
    }
    if (i < MEM) {
        int u = (int)i;
        float4 vb0 = { b0[u], b0[1024 + u], b0[2048 + u], b0[3072 + u] };
        float4 vb1 = { b1[u], b1[1024 + u], b1[2048 + u], b1[3072 + u] };
        *(float4*)&g_b0p[u * 4] = vb0;
        *(float4*)&g_b1p[u * 4] = vb1;
    }
}

// ---------------- transposed half weights WT[n][k] (gate-permuted n) ----------------
__global__ __launch_bounds__(256) void transpose_w2(const float* __restrict__ W, int sel) {
    __shared__ float s[32][33];
    int tx = threadIdx.x & 31, ty = threadIdx.x >> 5;
    int k0 = blockIdx.x * 32, c0 = blockIdx.y * 32;
    __half* dst = (sel == 0) ? g_W0t : g_W1t;
    long wst = (sel == 0) ? (VV + MEM) : (2 * MEM);
#pragma unroll
    for (int j = 0; j < 4; j++)
        s[ty + j * 8][tx] = W[(size_t)(k0 + ty + j * 8) * G4 + c0 + tx];
    __syncthreads();
#pragma unroll
    for (int j = 0; j < 4; j++) {
        int c = c0 + ty + j * 8;
        int n = (c & 1023) * 4 + (c >> 10);
        dst[(size_t)n * wst + k0 + tx] = __float2half_rn(s[tx][ty + j * 8]);
    }
}

__global__ __launch_bounds__(256) void transpose_wout(const float* __restrict__ W) {
    __shared__ float s[32][33];
    int tx = threadIdx.x & 31, ty = threadIdx.x >> 5;
    int k0 = blockIdx.x * 32, c0 = blockIdx.y * 32;
#pragma unroll
    for (int j = 0; j < 4; j++)
        s[ty + j * 8][tx] = W[(size_t)(k0 + ty + j * 8) * VV + c0 + tx];
    __syncthreads();
#pragma unroll
    for (int j = 0; j < 4; j++) {
        int n = c0 + ty + j * 8;
        g_Wot[(size_t)n * MEM + k0 + tx] = __float2half_rn(s[tx][ty + j * 8]);
    }
}

// ---------------- fp16 mma GEMM (phases 1/3/5), unchanged from round 9 ----------------
__global__ __launch_bounds__(256) void gemm_mma(
    const float* __restrict__ Ain, long sb, long st,
    long wst, int K, int src_gh, int w_sel,
    float* __restrict__ Cout, const float* __restrict__ bias_ext,
    long ocb, long oct)
{
    const float* A = src_gh ? (const float*)g_hall : Ain;
    const __half* WT = (w_sel == 0) ? g_W0t : ((w_sel == 1) ? g_W1t : g_Wot);
    const float* bias = (w_sel == 0) ? g_b0p : ((w_sel == 1) ? g_b1p : bias_ext);
    float* C = (w_sel == 2) ? Cout : (float*)g_Zx;

    __shared__ uint32_t As[128 * 32];
    __shared__ uint32_t Bs[64 * 32];

    const int tid = threadIdx.x;
    const int wid = tid >> 5, lane = tid & 31;
    const int gid = lane >> 2, tig = lane & 3;
    const int wm = wid & 3, wn = wid >> 2;
    const long brow = (long)blockIdx.y * 128;
    const int bcol = blockIdx.x * 64;

    int a_sw[4];
    const float* a_ptr[4];
#pragma unroll
    for (int i = 0; i < 4; i++) {
        int f = tid + i * 256;
        int row = f >> 3, g4 = f & 7;
        a_sw[i] = row * 32 + ((g4 * 4) ^ ((row & 7) * 4));
        long r = brow + row;
        a_ptr[i] = A + (r & 63) * sb + (r >> 6) * st + g4 * 8;
    }
    int b_sw[2];
    const uint32_t* b_ptr[2];
#pragma unroll
    for (int i = 0; i < 2; i++) {
        int f = tid + i * 256;
        int n = f >> 3, g4 = f & 7;
        b_sw[i] = n * 32 + ((g4 * 4) ^ ((n & 7) * 4));
        b_ptr[i] = (const uint32_t*)(WT + (size_t)(bcol + n) * wst) + g4 * 4;
    }

    float acc[2][4][4];
#pragma unroll
    for (int mt = 0; mt < 2; mt++)
#pragma unroll
        for (int nt = 0; nt < 4; nt++)
#pragma unroll
            for (int q = 0; q < 4; q++) acc[mt][nt][q] = 0.0f;

    const int arow0 = wm * 32 + gid;
    const int nb0 = wn * 32 + gid;
    const int xg = gid * 4;

    for (int kb = 0; kb < K; kb += 64) {
        float4 alo[4], ahi[4];
        uint4 bv[2];
#pragma unroll
        for (int i = 0; i < 4; i++) {
            alo[i] = *(const float4*)(a_ptr[i] + kb);
            ahi[i] = *(const float4*)(a_ptr[i] + kb + 4);
        }
#pragma unroll
        for (int i = 0; i < 2; i++) bv[i] = *(const uint4*)(b_ptr[i] + kb / 2);
        __syncthreads();
#pragma unroll
        for (int i = 0; i < 4; i++) {
            uint4 v;
            v.x = pk(alo[i].x, alo[i].y);
            v.y = pk(alo[i].z, alo[i].w);
            v.z = pk(ahi[i].x, ahi[i].y);
            v.w = pk(ahi[i].z, ahi[i].w);
            *(uint4*)&As[a_sw[i]] = v;
        }
#pragma unroll
        for (int i = 0; i < 2; i++) *(uint4*)&Bs[b_sw[i]] = bv[i];
        __syncthreads();

#pragma unroll
        for (int ks = 0; ks < 4; ks++) {
            int p0 = (ks * 8 + tig) ^ xg;
            int p1 = (ks * 8 + tig + 4) ^ xg;
            uint32_t a[2][4];
#pragma unroll
            for (int mt = 0; mt < 2; mt++) {
                int r0 = (arow0 + mt * 16) * 32;
                a[mt][0] = As[r0 + p0];
                a[mt][1] = As[r0 + 256 + p0];
                a[mt][2] = As[r0 + p1];
                a[mt][3] = As[r0 + 256 + p1];
            }
#pragma unroll
            for (int nt = 0; nt < 4; nt++) {
                int n = (nb0 + nt * 8) * 32;
                uint32_t b0 = Bs[n + p0];
                uint32_t b1 = Bs[n + p1];
#pragma unroll
                for (int mt = 0; mt < 2; mt++)
                    mma16(acc[mt][nt], a[mt][0], a[mt][1], a[mt][2], a[mt][3], b0, b1);
            }
        }
        __syncthreads();
    }

#pragma unroll
    for (int mt = 0; mt < 2; mt++) {
        long r2 = brow + wm * 32 + mt * 16 + gid;
        long co0 = (r2 & 63) * ocb + (r2 >> 6) * oct;
        long r3 = r2 + 8;
        long co1 = (r3 & 63) * ocb + (r3 >> 6) * oct;
#pragma unroll
        for (int nt = 0; nt < 4; nt++) {
            int col = bcol + wn * 32 + nt * 8 + tig * 2;
            float bz0 = bias[col], bz1 = bias[col + 1];
            float2 v0 = { acc[mt][nt][0] + bz0, acc[mt][nt][1] + bz1 };
            float2 v1 = { acc[mt][nt][2] + bz0, acc[mt][nt][3] + bz1 };
            *(float2*)(C + co0 + col) = v0;
            *(float2*)(C + co1 + col) = v1;
        }
    }
}

// ---------------- persistent recurrence: whole-h smem staging, 2 waits/step ----------------
// smem bytes: W_s [0,65536) | As 16 x 8192 [65536,196608) (Zs 36864 aliased at 65536) | Zx 2 x 9216 [196608,215040)
#define SMB_AS 65536
#define SMB_ZX 196608
#define SMB_TOTAL 215040

__global__ __launch_bounds__(256) void lstm_layer_persist(int layer, int ep_base)
{
    extern __shared__ char dynraw[];
    uint32_t* W_s = (uint32_t*)dynraw;                 // [n][kp^swz], 32 x 512
    uint32_t* As_ = (uint32_t*)(dynraw + SMB_AS);      // 16 chunk buffers x 2048 u32
    float* Zs  = (float*)(dynraw + SMB_AS);            // alias: [q4][64][36], used post-compute
    float* Zx_base = (float*)(dynraw + SMB_ZX);        // 2 x [64][36]

    const uint32_t* Wh = (layer == 0) ? (g_W0h + (size_t)(VV / 2) * G4)
                                      : (g_W1h + (size_t)(MEM / 2) * G4);
    float* c_st = g_c[layer];
    const int bid = blockIdx.x;
    const int tid = threadIdx.x;
    const int n0 = bid * 32;

    const int wid = tid >> 5, lane = tid & 31;
    const int gid = lane >> 2, tig = lane & 3;
    const int kq = wid & 3;           // k quarter (128 pairs)
    const int wm = wid >> 2;          // m half (32 rows)
    const int xg = gid * 4;

    // preload W slice [32 n][512 kp], swizzled
    for (int idx = tid; idx < 32 * 512; idx += 256) {
        int kp = idx >> 5, n = idx & 31;
        W_s[n * 512 + (kp ^ ((n & 7) * 4))] = Wh[(size_t)kp * G4 + n0 + n];
    }

    const uint32_t sbase = smem_u32(dynraw);

    // Zx staging: g = tid + i*256: m=g>>3, c4=g&7 (fp32, stride 36)
    uint32_t zx_dst[2]; int zx_soff[2];
#pragma unroll
    for (int i = 0; i < 2; i++) {
        int g = tid + i * 256;
        int m = g >> 3, c4 = g & 7;
        zx_dst[i] = sbase + (uint32_t)SMB_ZX + (uint32_t)(m * 36 + c4 * 4) * 4u;
        zx_soff[i] = m * G4 + n0 + c4 * 4;
    }

    // fragment constants
    int a_base[2];
#pragma unroll
    for (int mt = 0; mt < 2; mt++)
        a_base[mt] = (wm * 32 + mt * 16 + gid) * 32;
    int b_nidx[4];
#pragma unroll
    for (int nt = 0; nt < 4; nt++)
        b_nidx[nt] = (nt * 8 + gid) * 512;

    // pointwise constants + c registers
    const int pm0 = tid >> 3, pj = tid & 7;
    const int ci0 = pm0 * MEM + bid * 8 + pj;
    const int ci1 = (pm0 + 32) * MEM + bid * 8 + pj;
    float creg0 = c_st[ci0], creg1 = c_st[ci1];

    // initial Zx[0] prefetch into buffer 0
#pragma unroll
    for (int i = 0; i < 2; i++) cpa16(zx_dst[i], g_Zx + zx_soff[i]);
    cpa_commit();
    __syncthreads();   // W_s ready

    for (int t = 0; t < TT; t++) {
        const uint32_t* hr = g_h2[layer][t & 1];
        __half* hw_h = (__half*)g_h2[layer][(t + 1) & 1];

        // stage the entire h [64 x 512 pairs] = 128 KB as two commit-groups of 8 kc each
#pragma unroll
        for (int i = 0; i < 32; i++) {
            int g = tid + i * 256;
            int kc = g >> 9;
            int r = g & 511;
            int row = r >> 3, sub = r & 7;
            int q = sub >> 1, k4 = sub & 1;
            uint32_t dst = sbase + (uint32_t)SMB_AS + (uint32_t)(kc * 8192)
                         + (uint32_t)(row * 32 + ((q * 8 + k4 * 4) ^ ((row & 7) * 4))) * 4u;
            cpa16(dst, hr + row * 512 + q * 128 + kc * 8 + k4 * 4);
            if (i == 15) cpa_commit();
        }
        cpa_commit();

        float acc[2][4][4];
#pragma unroll
        for (int mt = 0; mt < 2; mt++)
#pragma unroll
            for (int nt = 0; nt < 4; nt++)
#pragma unroll
                for (int q = 0; q < 4; q++) acc[mt][nt][q] = 0.0f;

        WAITG(1);            // Zx group + first h half complete
        __syncthreads();

#pragma unroll
        for (int kc = 0; kc < 16; kc++) {
            if (kc == 8) {
                WAITG(0);    // second h half complete
                __syncthreads();
            }
            const uint32_t* Ab = As_ + kc * 2048;
            int p0 = (kq * 8 + tig) ^ xg;
            int p1 = (kq * 8 + tig + 4) ^ xg;
            uint32_t a[2][4];
#pragma unroll
            for (int mt = 0; mt < 2; mt++) {
                a[mt][0] = Ab[a_base[mt] + p0];
                a[mt][1] = Ab[a_base[mt] + 256 + p0];
                a[mt][2] = Ab[a_base[mt] + p1];
                a[mt][3] = Ab[a_base[mt] + 256 + p1];
            }
            int kp0 = kq * 128 + kc * 8 + tig;
#pragma unroll
            for (int nt = 0; nt < 4; nt++) {
                uint32_t b0 = W_s[b_nidx[nt] + (kp0 ^ xg)];
                uint32_t b1 = W_s[b_nidx[nt] + ((kp0 + 4) ^ xg)];
#pragma unroll
                for (int mt = 0; mt < 2; mt++)
                    mma16(acc[mt][nt], a[mt][0], a[mt][1], a[mt][2], a[mt][3], b0, b1);
            }
        }

        // store split-K partials to Zs (aliases kc0-4 buffers; disjoint per warp, read after sync)
#pragma unroll
        for (int mt = 0; mt < 2; mt++) {
            int row = wm * 32 + mt * 16 + gid;
#pragma unroll
            for (int nt = 0; nt < 4; nt++) {
                int col = nt * 8 + tig * 2;
                *(float2*)&Zs[kq * 2304 + row * 36 + col] =
                    make_float2(acc[mt][nt][0], acc[mt][nt][1]);
                *(float2*)&Zs[kq * 2304 + (row + 8) * 36 + col] =
                    make_float2(acc[mt][nt][2], acc[mt][nt][3]);
            }
        }
        __syncthreads();

        // pointwise (Zx read from buffer t&1)
        const float* Zx_s = Zx_base + (t & 1) * 2304;
#pragma unroll
        for (int e = 0; e < 2; e++) {
            int m = pm0 + e * 32;
            int ci = e ? ci1 : ci0;
            float4 z = *(const float4*)&Zx_s[m * 36 + pj * 4];
#pragma unroll
            for (int q = 0; q < 4; q++) {
                float4 p = *(const float4*)&Zs[q * 2304 + m * 36 + pj * 4];
                z.x += p.x; z.y += p.y; z.z += p.z; z.w += p.w;
            }
            float c = e ? creg1 : creg0;
            float cn = c * sigm(z.z + 1.0f) + sigm(z.x) * tanhf(z.y);
            float hn = tanhf(cn) * sigm(z.w);
            if (e) creg1 = cn; else creg0 = cn;
            hw_h[m * MEM + bid * 8 + pj] = __float2half_rn(hn);
            g_hall[(size_t)t * BB * MEM + ci] = hn;
            if (t == TT - 1) g_hfin[layer][ci] = hn;
        }

        if (t + 1 < TT) {
            // prefetch Zx[t+1] into the other buffer (no sync needed: distinct buffer)
            const float* zxn = g_Zx + (size_t)(t + 1) * BB * G4;
            uint32_t zoff = (uint32_t)(((t + 1) & 1) * 9216);
#pragma unroll
            for (int i = 0; i < 2; i++) cpa16(zx_dst[i] + zoff, zxn + zx_soff[i]);
            cpa_commit();

            // grid barrier
            int want = ep_base + t + 1;
            if (tid == 0) {
                __threadfence();
                g_arrive[bid] = want;
            }
            if (tid < 128) {
                while (g_arrive[tid] < want) { }
            }
            __syncthreads();
        }
    }

    c_st[ci0] = creg0;
    c_st[ci1] = creg1;
}

// ---------------- pack final_state [2, B, 2*MEM] ----------------
__global__ void state_pack(float* __restrict__ out)
{
    int i = blockIdx.x * 256 + threadIdx.x;
    int l = i / (BB * 2 * MEM);
    int rem = i % (BB * 2 * MEM);
    int b = rem / (2 * MEM);
    int u = rem % (2 * MEM);
    out[i] = (u < MEM) ? g_c[l][b * MEM + u] : g_hfin[l][b * MEM + (u - MEM)];
}

extern "C" void kernel_launch(void* const* d_in, const int* in_sizes, int n_in,
                              void* d_out, int out_size)
{
    const float* x    = (const float*)d_in[0];
    const float* s0   = (const float*)d_in[1];
    const float* s1   = (const float*)d_in[2];
    const float* W0   = (const float*)d_in[3];
    const float* b0   = (const float*)d_in[4];
    const float* W1   = (const float*)d_in[5];
    const float* b1   = (const float*)d_in[6];
    const float* Wout = (const float*)d_in[7];
    const float* bout = (const float*)d_in[8];
    float* out = (float*)d_out;

    cudaFuncSetAttribute(lstm_layer_persist,
                         cudaFuncAttributeMaxDynamicSharedMemorySize, SMB_TOTAL);

    init_state<<<256, 256>>>(s0, s1);

    {
        size_t total = (size_t)((VV + MEM) / 2) * MEM + (size_t)MEM * MEM;
        int blocks = (int)((total + 255) / 256);
        permute_w<<<blocks, 256>>>(W0, b0, W1, b1);
    }
    transpose_w2<<<dim3((VV + MEM) / 32, G4 / 32), 256>>>(W0, 0);
    transpose_w2<<<dim3((2 * MEM) / 32, G4 / 32), 256>>>(W1, 1);
    transpose_wout<<<dim3(MEM / 32, VV / 32), 256>>>(Wout);

    // Phase 1: Zx = x @ W0[:256,:] + b0   (M=32768, N=4096, K=256)
    gemm_mma<<<dim3(64, 256), 256>>>(x, (long)TT * VV, (long)VV,
                                     (long)(VV + MEM), VV, 0, 0,
                                     nullptr, nullptr, (long)G4, (long)BB * G4);

    // Layer 0 recurrence
    lstm_layer_persist<<<128, 256, SMB_TOTAL>>>(0, 0);

    // Phase 3: Zx = h0_all @ W1[:1024,:] + b1   (M=32768, N=4096, K=1024)
    gemm_mma<<<dim3(64, 256), 256>>>(nullptr, (long)MEM, (long)BB * MEM,
                                     (long)(2 * MEM), MEM, 1, 1,
                                     nullptr, nullptr, (long)G4, (long)BB * G4);

    // Layer 1 recurrence
    lstm_layer_persist<<<128, 256, SMB_TOTAL>>>(1, TT);

    // Phase 5: out[b,t,:] = h1_all @ W_out + b_out   (M=32768, N=256, K=1024)
    gemm_mma<<<dim3(4, 256), 256>>>(nullptr, (long)MEM, (long)BB * MEM,
                                    (long)MEM, MEM, 1, 2,
                                    out, bout, (long)TT * VV, (long)VV);

    state_pack<<<1024, 256>>>(out + (size_t)BB * TT * VV);
}

// round 14
// speedup vs baseline: 1.2368x; 1.2368x over previous
#include <cuda_runtime.h>
#include <cuda_fp16.h>
#include <math.h>
#include <stdint.h>

#define BB 64
#define TT 512
#define VV 256
#define MEM 1024
#define G4 4096

// ---------------- device scratch ----------------
__device__ float g_Zx[(size_t)TT * BB * G4];            // input-side z (+bias), gate-permuted cols, fp32
__device__ float g_hall[(size_t)TT * BB * MEM];         // per-layer h sequence fp32 (reused)
__device__ float g_c[2][BB * MEM];                      // cell state per layer, fp32
__device__ uint32_t g_h2[2][2][BB * 512];               // h state as packed half2, double-buffered
__device__ float g_hfin[2][BB * MEM];                   // final-step h, fp32
__device__ uint32_t g_W0h[((VV + MEM) / 2) * G4];       // W0 packed half2 pairs along k, gate-permuted cols
__device__ uint32_t g_W1h[((2 * MEM) / 2) * G4];        // W1 same
__device__ __half g_W0t[(size_t)G4 * (VV + MEM)];       // W0^T [n][k] halves, gate-permuted n
__device__ __half g_W1t[(size_t)G4 * (2 * MEM)];        // W1^T
__device__ __half g_Wot[(size_t)VV * MEM];              // W_out^T [n][k] halves
__device__ float g_b0p[G4];
__device__ float g_b1p[G4];
__device__ volatile int g_arrive[128];                  // grid-barrier flags

__device__ __forceinline__ float sigm(float x) { return 1.0f / (1.0f + expf(-x)); }
__device__ __forceinline__ uint32_t pk(float a, float b) {
    __half2 h = __floats2half2_rn(a, b);
    return *(uint32_t*)&h;
}
__device__ __forceinline__ uint32_t smem_u32(const void* p) {
    uint32_t a;
    asm("{ .reg .u64 t; cvta.to.shared.u64 t, %1; cvt.u32.u64 %0, t; }" : "=r"(a) : "l"(p));
    return a;
}
__device__ __forceinline__ void cpa16(uint32_t dst, const void* src) {
    asm volatile("cp.async.cg.shared.global [%0], [%1], 16;" :: "r"(dst), "l"(src));
}
__device__ __forceinline__ void cpa_commit() { asm volatile("cp.async.commit_group;" ::: "memory"); }
#define WAITG(n) asm volatile("cp.async.wait_group %0;" :: "n"(n) : "memory")

// m16n8k16 fp16 mma, fp32 accum
__device__ __forceinline__ void mma16(float* d, uint32_t a0, uint32_t a1, uint32_t a2, uint32_t a3,
                                      uint32_t b0, uint32_t b1) {
    asm volatile("mma.sync.aligned.m16n8k16.row.col.f32.f16.f16.f32 "
                 "{%0,%1,%2,%3}, {%4,%5,%6,%7}, {%8,%9}, {%0,%1,%2,%3};"
                 : "+f"(d[0]), "+f"(d[1]), "+f"(d[2]), "+f"(d[3])
                 : "r"(a0), "r"(a1), "r"(a2), "r"(a3), "r"(b0), "r"(b1));
}

// ---------------- init ----------------
__global__ void init_state(const float* __restrict__ s0, const float* __restrict__ s1) {
    int i = blockIdx.x * 256 + threadIdx.x;
    int b = i >> 10, u = i & 1023;
    g_c[0][i] = s0[b * 2 * MEM + u];
    g_c[1][i] = s1[b * 2 * MEM + u];
    if (u < 512) {
        int kp = u;
        g_h2[0][0][b * 512 + kp] = pk(s0[b * 2 * MEM + MEM + 2 * kp], s0[b * 2 * MEM + MEM + 2 * kp + 1]);
        g_h2[1][0][b * 512 + kp] = pk(s1[b * 2 * MEM + MEM + 2 * kp], s1[b * 2 * MEM + MEM + 2 * kp + 1]);
    }
    if (blockIdx.x == 0 && threadIdx.x < 128) g_arrive[threadIdx.x] = 0;
}

// ---------------- gate-permuted packed-half2 K-major weights + fp32 permuted biases ----------------
__global__ void permute_w(const float* __restrict__ W0, const float* __restrict__ b0,
                          const float* __restrict__ W1, const float* __restrict__ b1) {
    size_t i = (size_t)blockIdx.x * 256 + threadIdx.x;
    const size_t n0 = (size_t)((VV + MEM) / 2) * MEM;
    const size_t n1 = (size_t)((2 * MEM) / 2) * MEM;
    if (i < n0) {
        size_t kp = i >> 10; int u = (int)(i & 1023);
        const float* s = W0 + (size_t)(2 * kp) * G4 + u;
        uint4 v;
        v.x = pk(s[0],    s[G4]);
        v.y = pk(s[1024], s[G4 + 1024]);
        v.z = pk(s[2048], s[G4 + 2048]);
        v.w = pk(s[3072], s[G4 + 3072]);
        *(uint4*)&g_W0h[kp * G4 + (size_t)u * 4] = v;
    } else if (i < n0 + n1) {
        size_t k = i - n0;
        size_t kp = k >> 10; int u = (int)(k & 1023);
        const float* s = W1 + (size_t)(2 * kp) * G4 + u;
        uint4 v;
        v.x = pk(s[0],    s[G4]);
        v.y = pk(s[1024], s[G4 + 1024]);
        v.z = pk(s[2048], s[G4 + 2048]);
        v.w = pk(s[3072], s[G4 + 3072]);
        *(uint4*)&g_W1h[kp * G4 + (size_t)u * 4] = v;
    }
    if (i < MEM) {
        int u = (int)i;
        float4 vb0 = { b0[u], b0[1024 + u], b0[2048 + u], b0[3072 + u] };
        float4 vb1 = { b1[u], b1[1024 + u], b1[2048 + u], b1[3072 + u] };
        *(float4*)&g_b0p[u * 4] = vb0;
        *(float4*)&g_b1p[u * 4] = vb1;
    }
}

// ---------------- transposed half weights WT[n][k] (gate-permuted n) ----------------
__global__ __launch_bounds__(256) void transpose_w2(const float* __restrict__ W, int sel) {
    __shared__ float s[32][33];
    int tx = threadIdx.x & 31, ty = threadIdx.x >> 5;
    int k0 = blockIdx.x * 32, c0 = blockIdx.y * 32;
    __half* dst = (sel == 0) ? g_W0t : g_W1t;
    long wst = (sel == 0) ? (VV + MEM) : (2 * MEM);
#pragma unroll
    for (int j = 0; j < 4; j++)
        s[ty + j * 8][tx] = W[(size_t)(k0 + ty + j * 8) * G4 + c0 + tx];
    __syncthreads();
#pragma unroll
    for (int j = 0; j < 4; j++) {
        int c = c0 + ty + j * 8;
        int n = (c & 1023) * 4 + (c >> 10);
        dst[(size_t)n * wst + k0 + tx] = __float2half_rn(s[tx][ty + j * 8]);
    }
}

__global__ __launch_bounds__(256) void transpose_wout(const float* __restrict__ W) {
    __shared__ float s[32][33];
    int tx = threadIdx.x & 31, ty = threadIdx.x >> 5;
    int k0 = blockIdx.x * 32, c0 = blockIdx.y * 32;
#pragma unroll
    for (int j = 0; j < 4; j++)
        s[ty + j * 8][tx] = W[(size_t)(k0 + ty + j * 8) * VV + c0 + tx];
    __syncthreads();
#pragma unroll
    for (int j = 0; j < 4; j++) {
        int n = c0 + ty + j * 8;
        g_Wot[(size_t)n * MEM + k0 + tx] = __float2half_rn(s[tx][ty + j * 8]);
    }
}

// ---------------- fp16 mma GEMM (phases 1/3/5), unchanged ----------------
__global__ __launch_bounds__(256) void gemm_mma(
    const float* __restrict__ Ain, long sb, long st,
    long wst, int K, int src_gh, int w_sel,
    float* __restrict__ Cout, const float* __restrict__ bias_ext,
    long ocb, long oct)
{
    const float* A = src_gh ? (const float*)g_hall : Ain;
    const __half* WT = (w_sel == 0) ? g_W0t : ((w_sel == 1) ? g_W1t : g_Wot);
    const float* bias = (w_sel == 0) ? g_b0p : ((w_sel == 1) ? g_b1p : bias_ext);
    float* C = (w_sel == 2) ? Cout : (float*)g_Zx;

    __shared__ uint32_t As[128 * 32];
    __shared__ uint32_t Bs[64 * 32];

    const int tid = threadIdx.x;
    const int wid = tid >> 5, lane = tid & 31;
    const int gid = lane >> 2, tig = lane & 3;
    const int wm = wid & 3, wn = wid >> 2;
    const long brow = (long)blockIdx.y * 128;
    const int bcol = blockIdx.x * 64;

    int a_sw[4];
    const float* a_ptr[4];
#pragma unroll
    for (int i = 0; i < 4; i++) {
        int f = tid + i * 256;
        int row = f >> 3, g4 = f & 7;
        a_sw[i] = row * 32 + ((g4 * 4) ^ ((row & 7) * 4));
        long r = brow + row;
        a_ptr[i] = A + (r & 63) * sb + (r >> 6) * st + g4 * 8;
    }
    int b_sw[2];
    const uint32_t* b_ptr[2];
#pragma unroll
    for (int i = 0; i < 2; i++) {
        int f = tid + i * 256;
        int n = f >> 3, g4 = f & 7;
        b_sw[i] = n * 32 + ((g4 * 4) ^ ((n & 7) * 4));
        b_ptr[i] = (const uint32_t*)(WT + (size_t)(bcol + n) * wst) + g4 * 4;
    }

    float acc[2][4][4];
#pragma unroll
    for (int mt = 0; mt < 2; mt++)
#pragma unroll
        for (int nt = 0; nt < 4; nt++)
#pragma unroll
            for (int q = 0; q < 4; q++) acc[mt][nt][q] = 0.0f;

    const int arow0 = wm * 32 + gid;
    const int nb0 = wn * 32 + gid;
    const int xg = gid * 4;

    for (int kb = 0; kb < K; kb += 64) {
        float4 alo[4], ahi[4];
        uint4 bv[2];
#pragma unroll
        for (int i = 0; i < 4; i++) {
            alo[i] = *(const float4*)(a_ptr[i] + kb);
            ahi[i] = *(const float4*)(a_ptr[i] + kb + 4);
        }
#pragma unroll
        for (int i = 0; i < 2; i++) bv[i] = *(const uint4*)(b_ptr[i] + kb / 2);
        __syncthreads();
#pragma unroll
        for (int i = 0; i < 4; i++) {
            uint4 v;
            v.x = pk(alo[i].x, alo[i].y);
            v.y = pk(alo[i].z, alo[i].w);
            v.z = pk(ahi[i].x, ahi[i].y);
            v.w = pk(ahi[i].z, ahi[i].w);
            *(uint4*)&As[a_sw[i]] = v;
        }
#pragma unroll
        for (int i = 0; i < 2; i++) *(uint4*)&Bs[b_sw[i]] = bv[i];
        __syncthreads();

#pragma unroll
        for (int ks = 0; ks < 4; ks++) {
            int p0 = (ks * 8 + tig) ^ xg;
            int p1 = (ks * 8 + tig + 4) ^ xg;
            uint32_t a[2][4];
#pragma unroll
            for (int mt = 0; mt < 2; mt++) {
                int r0 = (arow0 + mt * 16) * 32;
                a[mt][0] = As[r0 + p0];
                a[mt][1] = As[r0 + 256 + p0];
                a[mt][2] = As[r0 + p1];
                a[mt][3] = As[r0 + 256 + p1];
            }
#pragma unroll
            for (int nt = 0; nt < 4; nt++) {
                int n = (nb0 + nt * 8) * 32;
                uint32_t b0 = Bs[n + p0];
                uint32_t b1 = Bs[n + p1];
#pragma unroll
                for (int mt = 0; mt < 2; mt++)
                    mma16(acc[mt][nt], a[mt][0], a[mt][1], a[mt][2], a[mt][3], b0, b1);
            }
        }
        __syncthreads();
    }

#pragma unroll
    for (int mt = 0; mt < 2; mt++) {
        long r2 = brow + wm * 32 + mt * 16 + gid;
        long co0 = (r2 & 63) * ocb + (r2 >> 6) * oct;
        long r3 = r2 + 8;
        long co1 = (r3 & 63) * ocb + (r3 >> 6) * oct;
#pragma unroll
        for (int nt = 0; nt < 4; nt++) {
            int col = bcol + wn * 32 + nt * 8 + tig * 2;
            float bz0 = bias[col], bz1 = bias[col + 1];
            float2 v0 = { acc[mt][nt][0] + bz0, acc[mt][nt][1] + bz1 };
            float2 v1 = { acc[mt][nt][2] + bz0, acc[mt][nt][3] + bz1 };
            *(float2*)(C + co0 + col) = v0;
            *(float2*)(C + co1 + col) = v1;
        }
    }
}

// ---------------- persistent recurrence: global barrier + depth-2 pipeline, 8 buffers ----------------
// smem bytes: W_s [0,65536) | As 8 x 8192 [65536,131072) | Zs 36864 [131072,167936) | Zx 2 x 9216 [167936,186368)
#define SMB_AS 65536
#define SMB_ZS 131072
#define SMB_ZX 167936
#define SMB_TOTAL 186368

__global__ __launch_bounds__(256) void lstm_layer_persist(int layer, int ep_base)
{
    extern __shared__ char dynraw[];
    uint32_t* W_s = (uint32_t*)dynraw;                 // [n][kp^swz], 32 x 512
    uint32_t* As_ = (uint32_t*)(dynraw + SMB_AS);      // 8 chunk buffers x 2048 u32
    float* Zs  = (float*)(dynraw + SMB_ZS);            // [q4][64][36]
    float* Zx_base = (float*)(dynraw + SMB_ZX);        // 2 x [64][36]

    const uint32_t* Wh = (layer == 0) ? (g_W0h + (size_t)(VV / 2) * G4)
                                      : (g_W1h + (size_t)(MEM / 2) * G4);
    float* c_st = g_c[layer];
    const int bid = blockIdx.x;
    const int tid = threadIdx.x;
    const int n0 = bid * 32;

    const int wid = tid >> 5, lane = tid & 31;
    const int gid = lane >> 2, tig = lane & 3;
    const int kq = wid & 3;        // k quarter (128 pairs)
    const int wm = wid >> 2;       // m half (32 rows)
    const int xg = gid * 4;

    // preload W slice [32 n][512 kp], swizzled
    for (int idx = tid; idx < 32 * 512; idx += 256) {
        int kp = idx >> 5, n = idx & 31;
        W_s[n * 512 + (kp ^ ((n & 7) * 4))] = Wh[(size_t)kp * G4 + n0 + n];
    }

    const uint32_t sbase = smem_u32(dynraw);

    // h-chunk staging granules: i<2: g = tid + i*256: q=g>>7, row=(g>>1)&63, k4=g&1
    uint32_t a_dst[2]; int a_soff[2];
#pragma unroll
    for (int i = 0; i < 2; i++) {
        int g = tid + i * 256;
        int q = g >> 7, row = (g >> 1) & 63, k4 = g & 1;
        a_dst[i] = sbase + (uint32_t)SMB_AS + (uint32_t)(row * 32 + ((q * 8 + k4 * 4) ^ ((row & 7) * 4))) * 4u;
        a_soff[i] = row * 512 + q * 128 + k4 * 4;   // + kc*8 per chunk
    }
    // Zx staging (fp32, stride 36): g = tid + i*256: m=g>>3, c4=g&7
    uint32_t zx_dst[2]; int zx_soff[2];
#pragma unroll
    for (int i = 0; i < 2; i++) {
        int g = tid + i * 256;
        int m = g >> 3, c4 = g & 7;
        zx_dst[i] = sbase + (uint32_t)SMB_ZX + (uint32_t)(m * 36 + c4 * 4) * 4u;
        zx_soff[i] = m * G4 + n0 + c4 * 4;
    }

    // fragment constants
    int a_base[2];
#pragma unroll
    for (int mt = 0; mt < 2; mt++)
        a_base[mt] = (wm * 32 + mt * 16 + gid) * 32;
    int b_nidx[4];
#pragma unroll
    for (int nt = 0; nt < 4; nt++)
        b_nidx[nt] = (nt * 8 + gid) * 512;

    // pointwise constants + c registers
    const int pm0 = tid >> 3, pj = tid & 7;
    const int ci0 = pm0 * MEM + bid * 8 + pj;
    const int ci1 = (pm0 + 32) * MEM + bid * 8 + pj;
    float creg0 = c_st[ci0], creg1 = c_st[ci1];

    // initial Zx[0] prefetch into buffer 0
#pragma unroll
    for (int i = 0; i < 2; i++) cpa16(zx_dst[i], g_Zx + zx_soff[i]);
    cpa_commit();
    __syncthreads();   // W_s ready

    for (int t = 0; t < TT; t++) {
        const uint32_t* hr = g_h2[layer][t & 1];
        __half* hw_h = (__half*)g_h2[layer][(t + 1) & 1];

        // issue chunk j into buffer j%8
        auto issue = [&](int j) {
            uint32_t bo = (uint32_t)(j & 7) * 8192u;
#pragma unroll
            for (int i = 0; i < 2; i++)
                cpa16(a_dst[i] + bo, hr + a_soff[i] + j * 8);
        };

        // prologue: 2 groups of 2 chunks (depth-2 pipeline)
        issue(0); issue(1); cpa_commit();
        issue(2); issue(3); cpa_commit();

        float acc[2][4][4];
#pragma unroll
        for (int mt = 0; mt < 2; mt++)
#pragma unroll
            for (int nt = 0; nt < 4; nt++)
#pragma unroll
                for (int q = 0; q < 4; q++) acc[mt][nt][q] = 0.0f;

        for (int s = 0; s < 8; s++) {
            if (s < 6) { issue(2 * s + 4); issue(2 * s + 5); cpa_commit(); }
            if (s < 6)      { WAITG(2); }
            else if (s == 6){ WAITG(1); }
            else            { WAITG(0); }
            __syncthreads();
#pragma unroll
            for (int half = 0; half < 2; half++) {
                int j = 2 * s + half;
                const uint32_t* Ab = As_ + (j & 7) * 2048;
                int p0 = (kq * 8 + tig) ^ xg;
                int p1 = (kq * 8 + tig + 4) ^ xg;
                uint32_t a[2][4];
#pragma unroll
                for (int mt = 0; mt < 2; mt++) {
                    a[mt][0] = Ab[a_base[mt] + p0];
                    a[mt][1] = Ab[a_base[mt] + 256 + p0];
                    a[mt][2] = Ab[a_base[mt] + p1];
                    a[mt][3] = Ab[a_base[mt] + 256 + p1];
                }
                int kp0 = kq * 128 + j * 8 + tig;
#pragma unroll
                for (int nt = 0; nt < 4; nt++) {
                    uint32_t b0 = W_s[b_nidx[nt] + (kp0 ^ xg)];
                    uint32_t b1 = W_s[b_nidx[nt] + ((kp0 + 4) ^ xg)];
#pragma unroll
                    for (int mt = 0; mt < 2; mt++)
                        mma16(acc[mt][nt], a[mt][0], a[mt][1], a[mt][2], a[mt][3], b0, b1);
                }
            }
        }

        // store split-K partials
#pragma unroll
        for (int mt = 0; mt < 2; mt++) {
            int row = wm * 32 + mt * 16 + gid;
#pragma unroll
            for (int nt = 0; nt < 4; nt++) {
                int col = nt * 8 + tig * 2;
                *(float2*)&Zs[kq * 2304 + row * 36 + col] =
                    make_float2(acc[mt][nt][0], acc[mt][nt][1]);
                *(float2*)&Zs[kq * 2304 + (row + 8) * 36 + col] =
                    make_float2(acc[mt][nt][2], acc[mt][nt][3]);
            }
        }
        __syncthreads();

        // pointwise (Zx from buffer t&1)
        const float* Zx_s = Zx_base + (t & 1) * 2304;
#pragma unroll
        for (int e = 0; e < 2; e++) {
            int m = pm0 + e * 32;
            int ci = e ? ci1 : ci0;
            float4 z = *(const float4*)&Zx_s[m * 36 + pj * 4];
#pragma unroll
            for (int q = 0; q < 4; q++) {
                float4 p = *(const float4*)&Zs[q * 2304 + m * 36 + pj * 4];
                z.x += p.x; z.y += p.y; z.z += p.z; z.w += p.w;
            }
            float c = e ? creg1 : creg0;
            float cn = c * sigm(z.z + 1.0f) + sigm(z.x) * tanhf(z.y);
            float hn = tanhf(cn) * sigm(z.w);
            if (e) creg1 = cn; else creg0 = cn;
            hw_h[m * MEM + bid * 8 + pj] = __float2half_rn(hn);
            g_hall[(size_t)t * BB * MEM + ci] = hn;
            if (t == TT - 1) g_hfin[layer][ci] = hn;
        }

        if (t + 1 < TT) {
            // publish h: all-thread fence, sync, one flag store
            __threadfence();
            __syncthreads();
            int want = ep_base + t + 1;
            if (tid == 0) g_arrive[bid] = want;

            // prefetch Zx[t+1] into the other buffer (hides under barrier poll)
            const float* zxn = g_Zx + (size_t)(t + 1) * BB * G4;
            uint32_t zoff = (uint32_t)(((t + 1) & 1) * 9216);
#pragma unroll
            for (int i = 0; i < 2; i++) cpa16(zx_dst[i] + zoff, zxn + zx_soff[i]);
            cpa_commit();

            // grid barrier poll
            if (tid < 128) {
                while (g_arrive[tid] < want) { }
            }
            __syncthreads();
        }
    }

    c_st[ci0] = creg0;
    c_st[ci1] = creg1;
}

// ---------------- pack final_state [2, B, 2*MEM] ----------------
__global__ void state_pack(float* __restrict__ out)
{
    int i = blockIdx.x * 256 + threadIdx.x;
    int l = i / (BB * 2 * MEM);
    int rem = i % (BB * 2 * MEM);
    int b = rem / (2 * MEM);
    int u = rem % (2 * MEM);
    out[i] = (u < MEM) ? g_c[l][b * MEM + u] : g_hfin[l][b * MEM + (u - MEM)];
}

extern "C" void kernel_launch(void* const* d_in, const int* in_sizes, int n_in,
                              void* d_out, int out_size)
{
    const float* x    = (const float*)d_in[0];
    const float* s0   = (const float*)d_in[1];
    const float* s1   = (const float*)d_in[2];
    const float* W0   = (const float*)d_in[3];
    const float* b0   = (const float*)d_in[4];
    const float* W1   = (const float*)d_in[5];
    const float* b1   = (const float*)d_in[6];
    const float* Wout = (const float*)d_in[7];
    const float* bout = (const float*)d_in[8];
    float* out = (float*)d_out;

    cudaFuncSetAttribute(lstm_layer_persist,
                         cudaFuncAttributeMaxDynamicSharedMemorySize, SMB_TOTAL);

    init_state<<<256, 256>>>(s0, s1);

    {
        size_t total = (size_t)((VV + MEM) / 2) * MEM + (size_t)MEM * MEM;
        int blocks = (int)((total + 255) / 256);
        permute_w<<<blocks, 256>>>(W0, b0, W1, b1);
    }
    transpose_w2<<<dim3((VV + MEM) / 32, G4 / 32), 256>>>(W0, 0);
    transpose_w2<<<dim3((2 * MEM) / 32, G4 / 32), 256>>>(W1, 1);
    transpose_wout<<<dim3(MEM / 32, VV / 32), 256>>>(Wout);

    // Phase 1: Zx = x @ W0[:256,:] + b0   (M=32768, N=4096, K=256)
    gemm_mma<<<dim3(64, 256), 256>>>(x, (long)TT * VV, (long)VV,
                                     (long)(VV + MEM), VV, 0, 0,
                                     nullptr, nullptr, (long)G4, (long)BB * G4);

    // Layer 0 recurrence
    lstm_layer_persist<<<128, 256, SMB_TOTAL>>>(0, 0);

    // Phase 3: Zx = h0_all @ W1[:1024,:] + b1   (M=32768, N=4096, K=1024)
    gemm_mma<<<dim3(64, 256), 256>>>(nullptr, (long)MEM, (long)BB * MEM,
                                     (long)(2 * MEM), MEM, 1, 1,
                                     nullptr, nullptr, (long)G4, (long)BB * G4);

    // Layer 1 recurrence
    lstm_layer_persist<<<128, 256, SMB_TOTAL>>>(1, TT);

    // Phase 5: out[b,t,:] = h1_all @ W_out + b_out   (M=32768, N=256, K=1024)
    gemm_mma<<<dim3(4, 256), 256>>>(nullptr, (long)MEM, (long)BB * MEM,
                                    (long)MEM, MEM, 1, 2,
                                    out, bout, (long)TT * VV, (long)VV);

    state_pack<<<1024, 256>>>(out + (size_t)BB * TT * VV);
}

// round 15
// speedup vs baseline: 1.7494x; 1.4145x over previous
#include <cuda_runtime.h>
#include <cuda_fp16.h>
#include <math.h>
#include <stdint.h>

#define BB 64
#define TT 512
#define VV 256
#define MEM 1024
#define G4 4096

// ---------------- device scratch ----------------
__device__ float g_Zx[(size_t)TT * BB * G4];            // layer0 input-side z (+b0), gate-permuted cols, fp32
__device__ float g_hall[(size_t)TT * BB * MEM];         // h1 sequence fp32 (phase-5 input)
__device__ float g_c[2][BB * MEM];                      // cell state per layer, fp32
__device__ uint32_t g_h0[2][BB * 512];                  // h0 packed half2, double-buffered by step parity
__device__ uint32_t g_h1[2][BB * 512];                  // h1 packed half2
__device__ float g_hfin[2][BB * MEM];                   // final-step h, fp32
__device__ uint32_t g_W0h[((VV + MEM) / 2) * G4];       // W0 packed half2 pairs along k, gate-permuted cols
__device__ uint32_t g_W1h[((2 * MEM) / 2) * G4];        // W1 same
__device__ __half g_W0t[(size_t)G4 * (VV + MEM)];       // W0^T [n][k] halves, gate-permuted n (phase1 B)
__device__ __half g_W1t[(size_t)G4 * (2 * MEM)];        // W1^T [n][k] (streamed W1x source, u32 view)
__device__ __half g_Wot[(size_t)VV * MEM];              // W_out^T [n][k] halves
__device__ float g_b0p[G4];
__device__ float g_b1p[G4];
__device__ volatile int g_arrive[128];                  // grid-barrier flags

__device__ __forceinline__ float sigm(float x) { return 1.0f / (1.0f + expf(-x)); }
__device__ __forceinline__ uint32_t pk(float a, float b) {
    __half2 h = __floats2half2_rn(a, b);
    return *(uint32_t*)&h;
}
__device__ __forceinline__ uint32_t smem_u32(const void* p) {
    uint32_t a;
    asm("{ .reg .u64 t; cvta.to.shared.u64 t, %1; cvt.u32.u64 %0, t; }" : "=r"(a) : "l"(p));
    return a;
}
__device__ __forceinline__ void cpa16(uint32_t dst, const void* src) {
    asm volatile("cp.async.cg.shared.global [%0], [%1], 16;" :: "r"(dst), "l"(src));
}
__device__ __forceinline__ void cpa_commit() { asm volatile("cp.async.commit_group;" ::: "memory"); }
#define WAITG(n) asm volatile("cp.async.wait_group %0;" :: "n"(n) : "memory")

// m16n8k16 fp16 mma, fp32 accum
__device__ __forceinline__ void mma16(float* d, uint32_t a0, uint32_t a1, uint32_t a2, uint32_t a3,
                                      uint32_t b0, uint32_t b1) {
    asm volatile("mma.sync.aligned.m16n8k16.row.col.f32.f16.f16.f32 "
                 "{%0,%1,%2,%3}, {%4,%5,%6,%7}, {%8,%9}, {%0,%1,%2,%3};"
                 : "+f"(d[0]), "+f"(d[1]), "+f"(d[2]), "+f"(d[3])
                 : "r"(a0), "r"(a1), "r"(a2), "r"(a3), "r"(b0), "r"(b1));
}

// ---------------- init ----------------
__global__ void init_state(const float* __restrict__ s0, const float* __restrict__ s1) {
    int i = blockIdx.x * 256 + threadIdx.x;
    int b = i >> 10, u = i & 1023;
    g_c[0][i] = s0[b * 2 * MEM + u];
    g_c[1][i] = s1[b * 2 * MEM + u];
    if (u < 512) {
        int kp = u;
        // "step -1" state lives in buffer 1 (read parity of round 0 / round 1)
        g_h0[1][b * 512 + kp] = pk(s0[b * 2 * MEM + MEM + 2 * kp], s0[b * 2 * MEM + MEM + 2 * kp + 1]);
        g_h1[1][b * 512 + kp] = pk(s1[b * 2 * MEM + MEM + 2 * kp], s1[b * 2 * MEM + MEM + 2 * kp + 1]);
    }
    if (blockIdx.x == 0 && threadIdx.x < 128) g_arrive[threadIdx.x] = 0;
}

// ---------------- gate-permuted packed-half2 K-major weights + fp32 permuted biases ----------------
__global__ void permute_w(const float* __restrict__ W0, const float* __restrict__ b0,
                          const float* __restrict__ W1, const float* __restrict__ b1) {
    size_t i = (size_t)blockIdx.x * 256 + threadIdx.x;
    const size_t n0 = (size_t)((VV + MEM) / 2) * MEM;
    const size_t n1 = (size_t)((2 * MEM) / 2) * MEM;
    if (i < n0) {
        size_t kp = i >> 10; int u = (int)(i & 1023);
        const float* s = W0 + (size_t)(2 * kp) * G4 + u;
        uint4 v;
        v.x = pk(s[0],    s[G4]);
        v.y = pk(s[1024], s[G4 + 1024]);
        v.z = pk(s[2048], s[G4 + 2048]);
        v.w = pk(s[3072], s[G4 + 3072]);
        *(uint4*)&g_W0h[kp * G4 + (size_t)u * 4] = v;
    } else if (i < n0 + n1) {
        size_t k = i - n0;
        size_t kp = k >> 10; int u = (int)(k & 1023);
        const float* s = W1 + (size_t)(2 * kp) * G4 + u;
        uint4 v;
        v.x = pk(s[0],    s[G4]);
        v.y = pk(s[1024], s[G4 + 1024]);
        v.z = pk(s[2048], s[G4 + 2048]);
        v.w = pk(s[3072], s[G4 + 3072]);
        *(uint4*)&g_W1h[kp * G4 + (size_t)u * 4] = v;
    }
    if (i < MEM) {
        int u = (int)i;
        float4 vb0 = { b0[u], b0[1024 + u], b0[2048 + u], b0[3072 + u] };
        float4 vb1 = { b1[u], b1[1024 + u], b1[2048 + u], b1[3072 + u] };
        *(float4*)&g_b0p[u * 4] = vb0;
        *(float4*)&g_b1p[u * 4] = vb1;
    }
}

// ---------------- transposed half weights WT[n][k] (gate-permuted n) ----------------
__global__ __launch_bounds__(256) void transpose_w2(const float* __restrict__ W, int sel) {
    __shared__ float s[32][33];
    int tx = threadIdx.x & 31, ty = threadIdx.x >> 5;
    int k0 = blockIdx.x * 32, c0 = blockIdx.y * 32;
    __half* dst = (sel == 0) ? g_W0t : g_W1t;
    long wst = (sel == 0) ? (VV + MEM) : (2 * MEM);
#pragma unroll
    for (int j = 0; j < 4; j++)
        s[ty + j * 8][tx] = W[(size_t)(k0 + ty + j * 8) * G4 + c0 + tx];
    __syncthreads();
#pragma unroll
    for (int j = 0; j < 4; j++) {
        int c = c0 + ty + j * 8;
        int n = (c & 1023) * 4 + (c >> 10);
        dst[(size_t)n * wst + k0 + tx] = __float2half_rn(s[tx][ty + j * 8]);
    }
}

__global__ __launch_bounds__(256) void transpose_wout(const float* __restrict__ W) {
    __shared__ float s[32][33];
    int tx = threadIdx.x & 31, ty = threadIdx.x >> 5;
    int k0 = blockIdx.x * 32, c0 = blockIdx.y * 32;
#pragma unroll
    for (int j = 0; j < 4; j++)
        s[ty + j * 8][tx] = W[(size_t)(k0 + ty + j * 8) * VV + c0 + tx];
    __syncthreads();
#pragma unroll
    for (int j = 0; j < 4; j++) {
        int n = c0 + ty + j * 8;
        g_Wot[(size_t)n * MEM + k0 + tx] = __float2half_rn(s[tx][ty + j * 8]);
    }
}

// ---------------- fp16 mma GEMM (phases 1/5), unchanged ----------------
__global__ __launch_bounds__(256) void gemm_mma(
    const float* __restrict__ Ain, long sb, long st,
    long wst, int K, int src_gh, int w_sel,
    float* __restrict__ Cout, const float* __restrict__ bias_ext,
    long ocb, long oct)
{
    const float* A = src_gh ? (const float*)g_hall : Ain;
    const __half* WT = (w_sel == 0) ? g_W0t : ((w_sel == 1) ? g_W1t : g_Wot);
    const float* bias = (w_sel == 0) ? g_b0p : ((w_sel == 1) ? g_b1p : bias_ext);
    float* C = (w_sel == 2) ? Cout : (float*)g_Zx;

    __shared__ uint32_t As[128 * 32];
    __shared__ uint32_t Bs[64 * 32];

    const int tid = threadIdx.x;
    const int wid = tid >> 5, lane = tid & 31;
    const int gid = lane >> 2, tig = lane & 3;
    const int wm = wid & 3, wn = wid >> 2;
    const long brow = (long)blockIdx.y * 128;
    const int bcol = blockIdx.x * 64;

    int a_sw[4];
    const float* a_ptr[4];
#pragma unroll
    for (int i = 0; i < 4; i++) {
        int f = tid + i * 256;
        int row = f >> 3, g4 = f & 7;
        a_sw[i] = row * 32 + ((g4 * 4) ^ ((row & 7) * 4));
        long r = brow + row;
        a_ptr[i] = A + (r & 63) * sb + (r >> 6) * st + g4 * 8;
    }
    int b_sw[2];
    const uint32_t* b_ptr[2];
#pragma unroll
    for (int i = 0; i < 2; i++) {
        int f = tid + i * 256;
        int n = f >> 3, g4 = f & 7;
        b_sw[i] = n * 32 + ((g4 * 4) ^ ((n & 7) * 4));
        b_ptr[i] = (const uint32_t*)(WT + (size_t)(bcol + n) * wst) + g4 * 4;
    }

    float acc[2][4][4];
#pragma unroll
    for (int mt = 0; mt < 2; mt++)
#pragma unroll
        for (int nt = 0; nt < 4; nt++)
#pragma unroll
            for (int q = 0; q < 4; q++) acc[mt][nt][q] = 0.0f;

    const int arow0 = wm * 32 + gid;
    const int nb0 = wn * 32 + gid;
    const int xg = gid * 4;

    for (int kb = 0; kb < K; kb += 64) {
        float4 alo[4], ahi[4];
        uint4 bv[2];
#pragma unroll
        for (int i = 0; i < 4; i++) {
            alo[i] = *(const float4*)(a_ptr[i] + kb);
            ahi[i] = *(const float4*)(a_ptr[i] + kb + 4);
        }
#pragma unroll
        for (int i = 0; i < 2; i++) bv[i] = *(const uint4*)(b_ptr[i] + kb / 2);
        __syncthreads();
#pragma unroll
        for (int i = 0; i < 4; i++) {
            uint4 v;
            v.x = pk(alo[i].x, alo[i].y);
            v.y = pk(alo[i].z, alo[i].w);
            v.z = pk(ahi[i].x, ahi[i].y);
            v.w = pk(ahi[i].z, ahi[i].w);
            *(uint4*)&As[a_sw[i]] = v;
        }
#pragma unroll
        for (int i = 0; i < 2; i++) *(uint4*)&Bs[b_sw[i]] = bv[i];
        __syncthreads();

#pragma unroll
        for (int ks = 0; ks < 4; ks++) {
            int p0 = (ks * 8 + tig) ^ xg;
            int p1 = (ks * 8 + tig + 4) ^ xg;
            uint32_t a[2][4];
#pragma unroll
            for (int mt = 0; mt < 2; mt++) {
                int r0 = (arow0 + mt * 16) * 32;
                a[mt][0] = As[r0 + p0];
                a[mt][1] = As[r0 + 256 + p0];
                a[mt][2] = As[r0 + p1];
                a[mt][3] = As[r0 + 256 + p1];
            }
#pragma unroll
            for (int nt = 0; nt < 4; nt++) {
                int n = (nb0 + nt * 8) * 32;
                uint32_t b0 = Bs[n + p0];
                uint32_t b1 = Bs[n + p1];
#pragma unroll
                for (int mt = 0; mt < 2; mt++)
                    mma16(acc[mt][nt], a[mt][0], a[mt][1], a[mt][2], a[mt][3], b0, b1);
            }
        }
        __syncthreads();
    }

#pragma unroll
    for (int mt = 0; mt < 2; mt++) {
        long r2 = brow + wm * 32 + mt * 16 + gid;
        long co0 = (r2 & 63) * ocb + (r2 >> 6) * oct;
        long r3 = r2 + 8;
        long co1 = (r3 & 63) * ocb + (r3 >> 6) * oct;
#pragma unroll
        for (int nt = 0; nt < 4; nt++) {
            int col = bcol + wn * 32 + nt * 8 + tig * 2;
            float bz0 = bias[col], bz1 = bias[col + 1];
            float2 v0 = { acc[mt][nt][0] + bz0, acc[mt][nt][1] + bz1 };
            float2 v1 = { acc[mt][nt][2] + bz0, acc[mt][nt][3] + bz1 };
            *(float2*)(C + co0 + col) = v0;
            *(float2*)(C + co1 + col) = v1;
        }
    }
}

// ---------------- fused two-layer persistent recurrence: 513 rounds ----------------
// Round r: layer0 step r (r<512) AND layer1 step r-1 (r>=1), same 32-col slice of both layers.
// smem: W0h res [0,64K) | W1h res [64K,128K) | Hbuf 4x8K [128K,160K) | Wbuf 4x4K [160K,176K)
//       | Zs 36864 [176K, +36864) | Zx 9216
#define SMB_W1   65536
#define SMB_HBUF 131072
#define SMB_WBUF 163840
#define SMB_ZS   180224
#define SMB_ZX   217088
#define SMB_TOT2 226304

__global__ __launch_bounds__(256) void lstm_fused()
{
    extern __shared__ char dynraw[];
    uint32_t* W0_s = (uint32_t*)dynraw;                    // [32n][512kp^swz]
    uint32_t* W1_s = (uint32_t*)(dynraw + SMB_W1);         // [32n][512kp^swz]
    uint32_t* Hb = (uint32_t*)(dynraw + SMB_HBUF);         // 4 x 2048 u32
    uint32_t* Wb = (uint32_t*)(dynraw + SMB_WBUF);         // 4 x 1024 u32
    float* Zs  = (float*)(dynraw + SMB_ZS);                // [q4][64][36]
    float* Zx_s = (float*)(dynraw + SMB_ZX);               // [64][36]

    const int bid = blockIdx.x;
    const int tid = threadIdx.x;
    const int n0 = bid * 32;

    const int wid = tid >> 5, lane = tid & 31;
    const int gid = lane >> 2, tig = lane & 3;
    const int kq = wid & 3;        // k quarter
    const int wm = wid >> 2;       // m half
    const int xg = gid * 4;

    // preload resident W slices (h-parts), swizzled
    {
        const uint32_t* Wh0 = g_W0h + (size_t)(VV / 2) * G4;
        const uint32_t* Wh1 = g_W1h + (size_t)(MEM / 2) * G4;
        for (int idx = tid; idx < 32 * 512; idx += 256) {
            int kp = idx >> 5, n = idx & 31;
            int d = n * 512 + (kp ^ ((n & 7) * 4));
            W0_s[d] = Wh0[(size_t)kp * G4 + n0 + n];
            W1_s[d] = Wh1[(size_t)kp * G4 + n0 + n];
        }
    }

    const uint32_t sbase = smem_u32(dynraw);

    // h-chunk staging granules (i<2): g = tid + i*256: q=g>>7, row=(g>>1)&63, k4=g&1
    uint32_t h_dst[2]; int h_soff[2];
#pragma unroll
    for (int i = 0; i < 2; i++) {
        int g = tid + i * 256;
        int q = g >> 7, row = (g >> 1) & 63, k4 = g & 1;
        h_dst[i] = sbase + (uint32_t)SMB_HBUF + (uint32_t)(row * 32 + ((q * 8 + k4 * 4) ^ ((row & 7) * 4))) * 4u;
        h_soff[i] = row * 512 + q * 128 + k4 * 4;   // + j*8 per chunk
    }
    // W1x chunk staging: one granule/thread: n=tid&31, q=(tid>>5)&3, k4=tid>>7
    uint32_t w_dst; size_t w_soff;
    {
        int n = tid & 31, q = (tid >> 5) & 3, k4 = tid >> 7;
        w_dst = sbase + (uint32_t)SMB_WBUF + (uint32_t)(n * 32 + ((q * 8 + k4 * 4) ^ ((n & 7) * 4))) * 4u;
        w_soff = (size_t)(n0 + n) * 1024 + q * 128 + k4 * 4;   // u32 units in g_W1t view, + j*8
    }
    const uint32_t* w1x_src = (const uint32_t*)g_W1t;

    // Zx staging (fp32, stride 36): g = tid + i*256: m=g>>3, c4=g&7
    uint32_t zx_dst[2]; int zx_soff[2];
#pragma unroll
    for (int i = 0; i < 2; i++) {
        int g = tid + i * 256;
        int m = g >> 3, c4 = g & 7;
        zx_dst[i] = sbase + (uint32_t)SMB_ZX + (uint32_t)(m * 36 + c4 * 4) * 4u;
        zx_soff[i] = m * G4 + n0 + c4 * 4;
    }

    // fragment constants
    int a_base[2];
#pragma unroll
    for (int mt = 0; mt < 2; mt++)
        a_base[mt] = (wm * 32 + mt * 16 + gid) * 32;
    int b_nidx[4], bc_nidx[4];
#pragma unroll
    for (int nt = 0; nt < 4; nt++) {
        b_nidx[nt] = (nt * 8 + gid) * 512;    // resident W stride
        bc_nidx[nt] = (nt * 8 + gid) * 32;    // chunk W stride
    }

    // pointwise constants + c registers
    const int pm0 = tid >> 3, pj = tid & 7;
    const int ci0 = pm0 * MEM + bid * 8 + pj;
    const int ci1 = (pm0 + 32) * MEM + bid * 8 + pj;
    float c0a = g_c[0][ci0], c0b = g_c[0][ci1];
    float c1a = g_c[1][ci0], c1b = g_c[1][ci1];

    // Zx[0] prefetch
#pragma unroll
    for (int i = 0; i < 2; i++) cpa16(zx_dst[i], g_Zx + zx_soff[i]);
    cpa_commit();
    __syncthreads();   // resident W ready

    for (int r = 0; r <= TT; r++) {
        const int rp = r & 1;
        const uint32_t* h0r = g_h0[1 - rp];     // h0_{r-1}
        const uint32_t* h1r = g_h1[rp];         // h1_{r-2}
        __half* h0w = (__half*)g_h0[rp];
        __half* h1w = (__half*)g_h1[1 - rp];

        // unit u: u<16 -> h0 chunk u (+ W1x chunk u); u>=16 -> h1 chunk u-16
        auto issue = [&](int u) {
            uint32_t hb = (uint32_t)(u & 3) * 8192u;
            if (u < 16) {
#pragma unroll
                for (int i = 0; i < 2; i++) cpa16(h_dst[i] + hb, h0r + h_soff[i] + u * 8);
                cpa16(w_dst + (uint32_t)(u & 3) * 4096u, w1x_src + w_soff + u * 8);
            } else {
                int j = u - 16;
#pragma unroll
                for (int i = 0; i < 2; i++) cpa16(h_dst[i] + hb, h1r + h_soff[i] + j * 8);
            }
        };

        issue(0); cpa_commit();
        issue(1); cpa_commit();

        float accL0[2][4][4], accL1[2][4][4];
#pragma unroll
        for (int mt = 0; mt < 2; mt++)
#pragma unroll
            for (int nt = 0; nt < 4; nt++)
#pragma unroll
                for (int q = 0; q < 4; q++) { accL0[mt][nt][q] = 0.0f; accL1[mt][nt][q] = 0.0f; }

        for (int u = 0; u < 32; u++) {
            if (u < 30) { issue(u + 2); cpa_commit(); }
            if (u < 30)      { WAITG(2); }
            else if (u == 30){ WAITG(1); }
            else             { WAITG(0); }
            __syncthreads();

            const uint32_t* Ab = Hb + (u & 3) * 2048;
            int p0 = (kq * 8 + tig) ^ xg;
            int p1 = (kq * 8 + tig + 4) ^ xg;
            uint32_t a[2][4];
#pragma unroll
            for (int mt = 0; mt < 2; mt++) {
                a[mt][0] = Ab[a_base[mt] + p0];
                a[mt][1] = Ab[a_base[mt] + 256 + p0];
                a[mt][2] = Ab[a_base[mt] + p1];
                a[mt][3] = Ab[a_base[mt] + 256 + p1];
            }
            if (u < 16) {
                int kp0 = kq * 128 + u * 8 + tig;
                const uint32_t* Wc = Wb + (u & 3) * 1024;
                int pp0 = kq * 8 + tig;
#pragma unroll
                for (int nt = 0; nt < 4; nt++) {
                    uint32_t b0 = W0_s[b_nidx[nt] + (kp0 ^ xg)];
                    uint32_t b1 = W0_s[b_nidx[nt] + ((kp0 + 4) ^ xg)];
                    uint32_t c0 = Wc[bc_nidx[nt] + (pp0 ^ xg)];
                    uint32_t c1 = Wc[bc_nidx[nt] + ((pp0 + 4) ^ xg)];
#pragma unroll
                    for (int mt = 0; mt < 2; mt++) {
                        mma16(accL0[mt][nt], a[mt][0], a[mt][1], a[mt][2], a[mt][3], b0, b1);
                        mma16(accL1[mt][nt], a[mt][0], a[mt][1], a[mt][2], a[mt][3], c0, c1);
                    }
                }
            } else {
                int j = u - 16;
                int kp0 = kq * 128 + j * 8 + tig;
#pragma unroll
                for (int nt = 0; nt < 4; nt++) {
                    uint32_t b0 = W1_s[b_nidx[nt] + (kp0 ^ xg)];
                    uint32_t b1 = W1_s[b_nidx[nt] + ((kp0 + 4) ^ xg)];
#pragma unroll
                    for (int mt = 0; mt < 2; mt++)
                        mma16(accL1[mt][nt], a[mt][0], a[mt][1], a[mt][2], a[mt][3], b0, b1);
                }
            }
        }

        // ---- layer0 pointwise (step r), skipped at r == TT ----
        if (r < TT) {
#pragma unroll
            for (int mt = 0; mt < 2; mt++) {
                int row = wm * 32 + mt * 16 + gid;
#pragma unroll
                for (int nt = 0; nt < 4; nt++) {
                    int col = nt * 8 + tig * 2;
                    *(float2*)&Zs[kq * 2304 + row * 36 + col] =
                        make_float2(accL0[mt][nt][0], accL0[mt][nt][1]);
                    *(float2*)&Zs[kq * 2304 + (row + 8) * 36 + col] =
                        make_float2(accL0[mt][nt][2], accL0[mt][nt][3]);
                }
            }
            __syncthreads();
#pragma unroll
            for (int e = 0; e < 2; e++) {
                int m = pm0 + e * 32;
                int ci = e ? ci1 : ci0;
                float4 z = *(const float4*)&Zx_s[m * 36 + pj * 4];
#pragma unroll
                for (int q = 0; q < 4; q++) {
                    float4 p = *(const float4*)&Zs[q * 2304 + m * 36 + pj * 4];
                    z.x += p.x; z.y += p.y; z.z += p.z; z.w += p.w;
                }
                float c = e ? c0b : c0a;
                float cn = c * sigm(z.z + 1.0f) + sigm(z.x) * tanhf(z.y);
                float hn = tanhf(cn) * sigm(z.w);
                if (e) c0b = cn; else c0a = cn;
                h0w[m * MEM + bid * 8 + pj] = __float2half_rn(hn);
                if (r == TT - 1) g_hfin[0][ci] = hn;
            }
            __syncthreads();   // Zs reuse
        }

        // ---- layer1 pointwise (step r-1), skipped at r == 0 ----
        if (r >= 1) {
            const int t1 = r - 1;
#pragma unroll
            for (int mt = 0; mt < 2; mt++) {
                int row = wm * 32 + mt * 16 + gid;
#pragma unroll
                for (int nt = 0; nt < 4; nt++) {
                    int col = nt * 8 + tig * 2;
                    *(float2*)&Zs[kq * 2304 + row * 36 + col] =
                        make_float2(accL1[mt][nt][0], accL1[mt][nt][1]);
                    *(float2*)&Zs[kq * 2304 + (row + 8) * 36 + col] =
                        make_float2(accL1[mt][nt][2], accL1[mt][nt][3]);
                }
            }
            __syncthreads();
            float4 bb = *(const float4*)&g_b1p[n0 + pj * 4];
#pragma unroll
            for (int e = 0; e < 2; e++) {
                int m = pm0 + e * 32;
                int ci = e ? ci1 : ci0;
                float4 z = bb;
#pragma unroll
                for (int q = 0; q < 4; q++) {
                    float4 p = *(const float4*)&Zs[q * 2304 + m * 36 + pj * 4];
                    z.x += p.x; z.y += p.y; z.z += p.z; z.w += p.w;
                }
                float c = e ? c1b : c1a;
                float cn = c * sigm(z.z + 1.0f) + sigm(z.x) * tanhf(z.y);
                float hn = tanhf(cn) * sigm(z.w);
                if (e) c1b = cn; else c1a = cn;
                h1w[m * MEM + bid * 8 + pj] = __float2half_rn(hn);
                g_hall[(size_t)t1 * BB * MEM + ci] = hn;
                if (t1 == TT - 1) g_hfin[1][ci] = hn;
            }
        }

        // ---- publish + barrier (not needed after the last round) ----
        if (r < TT) {
            __threadfence();
            __syncthreads();
            int want = r + 1;
            if (tid == 0) g_arrive[bid] = want;

            if (r + 1 < TT) {
                const float* zxn = g_Zx + (size_t)(r + 1) * BB * G4;
#pragma unroll
                for (int i = 0; i < 2; i++) cpa16(zx_dst[i], zxn + zx_soff[i]);
                cpa_commit();
            }

            if (tid < 128) {
                while (g_arrive[tid] < want) { }
            }
            __syncthreads();
        }
    }

    g_c[0][ci0] = c0a; g_c[0][ci1] = c0b;
    g_c[1][ci0] = c1a; g_c[1][ci1] = c1b;
}

// ---------------- pack final_state [2, B, 2*MEM] ----------------
__global__ void state_pack(float* __restrict__ out)
{
    int i = blockIdx.x * 256 + threadIdx.x;
    int l = i / (BB * 2 * MEM);
    int rem = i % (BB * 2 * MEM);
    int b = rem / (2 * MEM);
    int u = rem % (2 * MEM);
    out[i] = (u < MEM) ? g_c[l][b * MEM + u] : g_hfin[l][b * MEM + (u - MEM)];
}

extern "C" void kernel_launch(void* const* d_in, const int* in_sizes, int n_in,
                              void* d_out, int out_size)
{
    const float* x    = (const float*)d_in[0];
    const float* s0   = (const float*)d_in[1];
    const float* s1   = (const float*)d_in[2];
    const float* W0   = (const float*)d_in[3];
    const float* b0   = (const float*)d_in[4];
    const float* W1   = (const float*)d_in[5];
    const float* b1   = (const float*)d_in[6];
    const float* Wout = (const float*)d_in[7];
    const float* bout = (const float*)d_in[8];
    float* out = (float*)d_out;

    cudaFuncSetAttribute(lstm_fused,
                         cudaFuncAttributeMaxDynamicSharedMemorySize, SMB_TOT2);

    init_state<<<256, 256>>>(s0, s1);

    {
        size_t total = (size_t)((VV + MEM) / 2) * MEM + (size_t)MEM * MEM;
        int blocks = (int)((total + 255) / 256);
        permute_w<<<blocks, 256>>>(W0, b0, W1, b1);
    }
    transpose_w2<<<dim3((VV + MEM) / 32, G4 / 32), 256>>>(W0, 0);
    transpose_w2<<<dim3((2 * MEM) / 32, G4 / 32), 256>>>(W1, 1);
    transpose_wout<<<dim3(MEM / 32, VV / 32), 256>>>(Wout);

    // Phase 1: Zx = x @ W0[:256,:] + b0   (M=32768, N=4096, K=256)
    gemm_mma<<<dim3(64, 256), 256>>>(x, (long)TT * VV, (long)VV,
                                     (long)(VV + MEM), VV, 0, 0,
                                     nullptr, nullptr, (long)G4, (long)BB * G4);

    // Fused two-layer recurrence: 513 rounds, one launch
    lstm_fused<<<128, 256, SMB_TOT2>>>();

    // Phase 5: out[b,t,:] = h1_all @ W_out + b_out   (M=32768, N=256, K=1024)
    gemm_mma<<<dim3(4, 256), 256>>>(nullptr, (long)MEM, (long)BB * MEM,
                                    (long)MEM, MEM, 1, 2,
                                    out, bout, (long)TT * VV, (long)VV);

    state_pack<<<1024, 256>>>(out + (size_t)BB * TT * VV);
}